// round 3
// baseline (speedup 1.0000x reference)
#include <cuda_runtime.h>
#include <math.h>
#include <math_constants.h>

#ifndef CUDART_INF_F
#define CUDART_INF_F __int_as_float(0x7f800000)
#endif

// ---------------------------------------------------------------------------
// AdaptivePrecisionKVCache: global two-bin min/max reduction + elementwise
// quantize/dequantize.
//   small bin: |x| <= 0.01, levels = 15
//   large bin: |x| >  0.01, levels = 255
//   valid bin <=> bmin < bmax  (covers empty-bin and constant-bin cases)
// Pipeline: k_reduce (per-block partials) -> k_finalize (single block, computes
// params) -> k_dequant (streaming float4 elementwise).
// All scratch is __device__ globals (no allocation); all launches are plain
// kernels on the capture stream (graph-capturable, deterministic).
// ---------------------------------------------------------------------------

#define THRESH 0.01f
#define RED_BLOCKS 2368          // 148 SMs * 16
#define RED_THREADS 256
#define DQ_THREADS 256

__device__ float4 g_partials[RED_BLOCKS];  // x=smin, y=smax, z=lmin, w=lmax
__device__ float4 g_ps;                    // smin, 15/sden, sden/15, svalid
__device__ float4 g_pl;                    // lmin, 255/lden, lden/255, lvalid

struct MM { float smin, smax, lmin, lmax; };

__device__ __forceinline__ void acc_val(float x, MM& m) {
    bool big = fabsf(x) > THRESH;
    // branchless bin-select via +-inf neutral elements
    float inf = CUDART_INF_F;
    m.smin = fminf(m.smin, big ?  inf : x);
    m.smax = fmaxf(m.smax, big ? -inf : x);
    m.lmin = fminf(m.lmin, big ? x :  inf);
    m.lmax = fmaxf(m.lmax, big ? x : -inf);
}

__device__ __forceinline__ void warp_reduce(MM& m) {
    #pragma unroll
    for (int o = 16; o > 0; o >>= 1) {
        m.smin = fminf(m.smin, __shfl_xor_sync(0xffffffffu, m.smin, o));
        m.smax = fmaxf(m.smax, __shfl_xor_sync(0xffffffffu, m.smax, o));
        m.lmin = fminf(m.lmin, __shfl_xor_sync(0xffffffffu, m.lmin, o));
        m.lmax = fmaxf(m.lmax, __shfl_xor_sync(0xffffffffu, m.lmax, o));
    }
}

__device__ __forceinline__ void block_reduce_and_store(MM m, float4* dst) {
    warp_reduce(m);
    __shared__ MM sm[RED_THREADS / 32];
    int w = threadIdx.x >> 5;
    if ((threadIdx.x & 31) == 0) sm[w] = m;
    __syncthreads();
    if (threadIdx.x == 0) {
        MM r = sm[0];
        #pragma unroll
        for (int i = 1; i < RED_THREADS / 32; i++) {
            r.smin = fminf(r.smin, sm[i].smin);
            r.smax = fmaxf(r.smax, sm[i].smax);
            r.lmin = fminf(r.lmin, sm[i].lmin);
            r.lmax = fmaxf(r.lmax, sm[i].lmax);
        }
        *dst = make_float4(r.smin, r.smax, r.lmin, r.lmax);
    }
}

__global__ void __launch_bounds__(RED_THREADS)
k_reduce(const float* __restrict__ in, int n) {
    float inf = CUDART_INF_F;
    MM m = { inf, -inf, inf, -inf };
    int nvec = n >> 2;
    const float4* __restrict__ in4 = (const float4*)in;
    int stride = gridDim.x * blockDim.x;
    for (int i = blockIdx.x * blockDim.x + threadIdx.x; i < nvec; i += stride) {
        float4 v = in4[i];
        acc_val(v.x, m); acc_val(v.y, m); acc_val(v.z, m); acc_val(v.w, m);
    }
    // scalar tail (n not multiple of 4)
    if (blockIdx.x == 0) {
        for (int j = (nvec << 2) + threadIdx.x; j < n; j += blockDim.x)
            acc_val(in[j], m);
    }
    block_reduce_and_store(m, &g_partials[blockIdx.x]);
}

__global__ void __launch_bounds__(RED_THREADS)
k_finalize() {
    float inf = CUDART_INF_F;
    MM m = { inf, -inf, inf, -inf };
    for (int i = threadIdx.x; i < RED_BLOCKS; i += blockDim.x) {
        float4 p = g_partials[i];
        m.smin = fminf(m.smin, p.x);
        m.smax = fmaxf(m.smax, p.y);
        m.lmin = fminf(m.lmin, p.z);
        m.lmax = fmaxf(m.lmax, p.w);
    }
    warp_reduce(m);
    __shared__ MM sm[RED_THREADS / 32];
    int w = threadIdx.x >> 5;
    if ((threadIdx.x & 31) == 0) sm[w] = m;
    __syncthreads();
    if (threadIdx.x == 0) {
        MM r = sm[0];
        #pragma unroll
        for (int i = 1; i < RED_THREADS / 32; i++) {
            r.smin = fminf(r.smin, sm[i].smin);
            r.smax = fmaxf(r.smax, sm[i].smax);
            r.lmin = fminf(r.lmin, sm[i].lmin);
            r.lmax = fmaxf(r.lmax, sm[i].lmax);
        }
        bool sv = r.smin < r.smax;
        float sd = sv ? (r.smax - r.smin) : 1.0f;
        g_ps = make_float4(r.smin, 15.0f / sd, sd / 15.0f, sv ? 1.0f : 0.0f);
        bool lv = r.lmin < r.lmax;
        float ld = lv ? (r.lmax - r.lmin) : 1.0f;
        g_pl = make_float4(r.lmin, 255.0f / ld, ld / 255.0f, lv ? 1.0f : 0.0f);
    }
}

__device__ __forceinline__ float dq(float x, float4 ps, float4 pl) {
    bool big = fabsf(x) > THRESH;
    float bmin = big ? pl.x : ps.x;
    float sc   = big ? pl.y : ps.y;
    float iv   = big ? pl.z : ps.z;
    float vd   = big ? pl.w : ps.w;
    float q = rintf((x - bmin) * sc);   // rintf == round-half-even == jnp.round
    float d = fmaf(q, iv, bmin);
    return (vd != 0.0f) ? d : x;
}

__global__ void __launch_bounds__(DQ_THREADS)
k_dequant(const float* __restrict__ in, float* __restrict__ out, int n) {
    const float4 ps = g_ps;
    const float4 pl = g_pl;
    int nvec = n >> 2;
    const float4* __restrict__ in4 = (const float4*)in;
    float4* __restrict__ out4 = (float4*)out;
    int stride = gridDim.x * blockDim.x;
    for (int i = blockIdx.x * blockDim.x + threadIdx.x; i < nvec; i += stride) {
        float4 v = in4[i];
        v.x = dq(v.x, ps, pl);
        v.y = dq(v.y, ps, pl);
        v.z = dq(v.z, ps, pl);
        v.w = dq(v.w, ps, pl);
        out4[i] = v;
    }
    if (blockIdx.x == 0) {
        for (int j = (nvec << 2) + threadIdx.x; j < n; j += blockDim.x)
            out[j] = dq(in[j], ps, pl);
    }
}

extern "C" void kernel_launch(void* const* d_in, const int* in_sizes, int n_in,
                              void* d_out, int out_size) {
    (void)n_in; (void)out_size;
    const float* in = (const float*)d_in[0];
    float* out = (float*)d_out;
    int n = in_sizes[0];

    int nvec = n >> 2;

    k_reduce<<<RED_BLOCKS, RED_THREADS>>>(in, n);
    k_finalize<<<1, RED_THREADS>>>();

    int dq_blocks = (nvec + DQ_THREADS - 1) / DQ_THREADS;
    if (dq_blocks < 1) dq_blocks = 1;
    k_dequant<<<dq_blocks, DQ_THREADS>>>(in, out, n);
}

// round 4
// speedup vs baseline: 1.1264x; 1.1264x over previous
#include <cuda_runtime.h>
#include <math.h>
#include <math_constants.h>

#ifndef CUDART_INF_F
#define CUDART_INF_F __int_as_float(0x7f800000)
#endif

// ---------------------------------------------------------------------------
// AdaptivePrecisionKVCache: global two-bin min/max reduction + elementwise
// quantize/dequantize.
//   small bin: |x| <= 0.01, levels = 15
//   large bin: |x| >  0.01, levels = 255
//   valid bin <=> bmin < bmax
// R3 changes:
//   - k_reduce: 4 independent LDG.128 per outer iter into 4 accumulator sets
//     (raise MLP, shorten FMNMX dependency chains).
//   - k_dequant: reversed block order so it starts on the array tail that
//     k_reduce just left resident in L2 (126MB L2 vs 134MB stream).
// ---------------------------------------------------------------------------

#define THRESH 0.01f
#define RED_BLOCKS 2368          // 148 SMs * 16
#define RED_THREADS 256
#define DQ_THREADS 256
#define DQ_UNROLL 2

__device__ float4 g_partials[RED_BLOCKS];  // x=smin, y=smax, z=lmin, w=lmax
__device__ float4 g_ps;                    // smin, 15/sden, sden/15, svalid
__device__ float4 g_pl;                    // lmin, 255/lden, lden/255, lvalid

struct MM { float smin, smax, lmin, lmax; };

__device__ __forceinline__ void mm_init(MM& m) {
    float inf = CUDART_INF_F;
    m.smin = inf; m.smax = -inf; m.lmin = inf; m.lmax = -inf;
}

__device__ __forceinline__ void acc_val(float x, MM& m) {
    bool big = fabsf(x) > THRESH;
    float inf = CUDART_INF_F;
    m.smin = fminf(m.smin, big ?  inf : x);
    m.smax = fmaxf(m.smax, big ? -inf : x);
    m.lmin = fminf(m.lmin, big ? x :  inf);
    m.lmax = fmaxf(m.lmax, big ? x : -inf);
}

__device__ __forceinline__ void acc_vec(float4 v, MM& m) {
    acc_val(v.x, m); acc_val(v.y, m); acc_val(v.z, m); acc_val(v.w, m);
}

__device__ __forceinline__ void mm_merge(MM& a, const MM& b) {
    a.smin = fminf(a.smin, b.smin);
    a.smax = fmaxf(a.smax, b.smax);
    a.lmin = fminf(a.lmin, b.lmin);
    a.lmax = fmaxf(a.lmax, b.lmax);
}

__device__ __forceinline__ void warp_reduce(MM& m) {
    #pragma unroll
    for (int o = 16; o > 0; o >>= 1) {
        m.smin = fminf(m.smin, __shfl_xor_sync(0xffffffffu, m.smin, o));
        m.smax = fmaxf(m.smax, __shfl_xor_sync(0xffffffffu, m.smax, o));
        m.lmin = fminf(m.lmin, __shfl_xor_sync(0xffffffffu, m.lmin, o));
        m.lmax = fmaxf(m.lmax, __shfl_xor_sync(0xffffffffu, m.lmax, o));
    }
}

__device__ __forceinline__ void block_reduce_and_store(MM m, float4* dst) {
    warp_reduce(m);
    __shared__ MM sm[RED_THREADS / 32];
    int w = threadIdx.x >> 5;
    if ((threadIdx.x & 31) == 0) sm[w] = m;
    __syncthreads();
    if (threadIdx.x == 0) {
        MM r = sm[0];
        #pragma unroll
        for (int i = 1; i < RED_THREADS / 32; i++) mm_merge(r, sm[i]);
        *dst = make_float4(r.smin, r.smax, r.lmin, r.lmax);
    }
}

__global__ void __launch_bounds__(RED_THREADS)
k_reduce(const float* __restrict__ in, int n) {
    MM m0, m1, m2, m3;
    mm_init(m0); mm_init(m1); mm_init(m2); mm_init(m3);
    int nvec = n >> 2;
    const float4* __restrict__ in4 = (const float4*)in;
    int S = gridDim.x * blockDim.x;          // total threads
    int tid = blockIdx.x * blockDim.x + threadIdx.x;
    // 4 independent batched loads per outer iteration
    int i = tid;
    for (; i + 3 * S < nvec; i += 4 * S) {
        float4 v0 = in4[i];
        float4 v1 = in4[i + S];
        float4 v2 = in4[i + 2 * S];
        float4 v3 = in4[i + 3 * S];
        acc_vec(v0, m0); acc_vec(v1, m1); acc_vec(v2, m2); acc_vec(v3, m3);
    }
    for (; i < nvec; i += S) acc_vec(in4[i], m0);
    // scalar tail (n not multiple of 4)
    if (blockIdx.x == 0) {
        for (int j = (nvec << 2) + threadIdx.x; j < n; j += blockDim.x)
            acc_val(in[j], m0);
    }
    mm_merge(m0, m1); mm_merge(m2, m3); mm_merge(m0, m2);
    block_reduce_and_store(m0, &g_partials[blockIdx.x]);
}

__global__ void __launch_bounds__(RED_THREADS)
k_finalize() {
    MM m; mm_init(m);
    for (int i = threadIdx.x; i < RED_BLOCKS; i += blockDim.x) {
        float4 p = g_partials[i];
        m.smin = fminf(m.smin, p.x);
        m.smax = fmaxf(m.smax, p.y);
        m.lmin = fminf(m.lmin, p.z);
        m.lmax = fmaxf(m.lmax, p.w);
    }
    warp_reduce(m);
    __shared__ MM sm[RED_THREADS / 32];
    int w = threadIdx.x >> 5;
    if ((threadIdx.x & 31) == 0) sm[w] = m;
    __syncthreads();
    if (threadIdx.x == 0) {
        MM r = sm[0];
        #pragma unroll
        for (int i = 1; i < RED_THREADS / 32; i++) mm_merge(r, sm[i]);
        bool sv = r.smin < r.smax;
        float sd = sv ? (r.smax - r.smin) : 1.0f;
        g_ps = make_float4(r.smin, 15.0f / sd, sd / 15.0f, sv ? 1.0f : 0.0f);
        bool lv = r.lmin < r.lmax;
        float ld = lv ? (r.lmax - r.lmin) : 1.0f;
        g_pl = make_float4(r.lmin, 255.0f / ld, ld / 255.0f, lv ? 1.0f : 0.0f);
    }
}

__device__ __forceinline__ float dq(float x, float4 ps, float4 pl) {
    bool big = fabsf(x) > THRESH;
    float bmin = big ? pl.x : ps.x;
    float sc   = big ? pl.y : ps.y;
    float iv   = big ? pl.z : ps.z;
    float vd   = big ? pl.w : ps.w;
    float q = rintf((x - bmin) * sc);   // rintf == round-half-even == jnp.round
    float d = fmaf(q, iv, bmin);
    return (vd != 0.0f) ? d : x;
}

__device__ __forceinline__ float4 dq4(float4 v, float4 ps, float4 pl) {
    v.x = dq(v.x, ps, pl);
    v.y = dq(v.y, ps, pl);
    v.z = dq(v.z, ps, pl);
    v.w = dq(v.w, ps, pl);
    return v;
}

// Reversed block order: start on the tail that k_reduce left hot in L2.
__global__ void __launch_bounds__(DQ_THREADS)
k_dequant(const float* __restrict__ in, float* __restrict__ out, int n) {
    const float4 ps = g_ps;
    const float4 pl = g_pl;
    int nvec = n >> 2;
    const float4* __restrict__ in4 = (const float4*)in;
    float4* __restrict__ out4 = (float4*)out;
    // Block rb covers chunk of DQ_UNROLL*DQ_THREADS vecs; reverse block order.
    int rb = gridDim.x - 1 - blockIdx.x;
    int base = rb * (DQ_UNROLL * DQ_THREADS) + threadIdx.x;
    int i0 = base;
    int i1 = base + DQ_THREADS;
    float4 v0, v1;
    bool ok0 = i0 < nvec;
    bool ok1 = i1 < nvec;
    if (ok0) v0 = in4[i0];
    if (ok1) v1 = in4[i1];
    if (ok0) out4[i0] = dq4(v0, ps, pl);
    if (ok1) out4[i1] = dq4(v1, ps, pl);
    // scalar tail (n not multiple of 4) — handled by the first-launched block
    if (blockIdx.x == 0) {
        for (int j = (nvec << 2) + threadIdx.x; j < n; j += blockDim.x)
            out[j] = dq(in[j], ps, pl);
    }
}

extern "C" void kernel_launch(void* const* d_in, const int* in_sizes, int n_in,
                              void* d_out, int out_size) {
    (void)n_in; (void)out_size;
    const float* in = (const float*)d_in[0];
    float* out = (float*)d_out;
    int n = in_sizes[0];

    int nvec = n >> 2;

    k_reduce<<<RED_BLOCKS, RED_THREADS>>>(in, n);
    k_finalize<<<1, RED_THREADS>>>();

    int chunk = DQ_UNROLL * DQ_THREADS;
    int dq_blocks = (nvec + chunk - 1) / chunk;
    if (dq_blocks < 1) dq_blocks = 1;
    k_dequant<<<dq_blocks, DQ_THREADS>>>(in, out, n);
}